// round 11
// baseline (speedup 1.0000x reference)
#include <cuda_runtime.h>
#include <cuda_bf16.h>
#include <cstdint>
#include <math.h>

using bf16 = __nv_bfloat16;

// B=8, S=2048, D=1024
// ---------------------------------------------------------------------------
// Device scratch (allocation-free rule: __device__ globals)
// ---------------------------------------------------------------------------
__device__ __align__(16) bf16  g_xb [16384LL*1024];
__device__ __align__(16) bf16  g_wq [1024LL*1024];
__device__ __align__(16) bf16  g_wk [1024LL*1024];
__device__ __align__(16) bf16  g_wv [1024LL*1024];
__device__ __align__(16) bf16  g_wo [1024LL*1024];
__device__ __align__(16) bf16  g_q  [16384LL*1024];
__device__ __align__(16) bf16  g_k  [16384LL*1024];
__device__ __align__(16) bf16  g_v  [16384LL*1024];
__device__ __align__(16) bf16  g_vt [8LL*1024*2048];   // [b][h][s]
__device__ __align__(16) bf16  g_s  [8LL*2048*2048];   // scores / attn
__device__ __align__(16) bf16  g_w  [16384LL*1024];    // weighted
__device__ __align__(16) float g_pre[16384LL*1024];    // pre-LayerNorm

// ---------------------------------------------------------------------------
// fp32 -> bf16 convert (vectorized)
// ---------------------------------------------------------------------------
__global__ void cvt_k(const float4* __restrict__ in, uint2* __restrict__ out, int n4) {
    for (int i = blockIdx.x * blockDim.x + threadIdx.x; i < n4;
         i += gridDim.x * blockDim.x) {
        float4 f = in[i];
        uint2 o;
        __nv_bfloat162 lo = __floats2bfloat162_rn(f.x, f.y);
        __nv_bfloat162 hi = __floats2bfloat162_rn(f.z, f.w);
        o.x = *reinterpret_cast<uint32_t*>(&lo);
        o.y = *reinterpret_cast<uint32_t*>(&hi);
        out[i] = o;
    }
}

// ---------------------------------------------------------------------------
// Per-batch transpose: out[b][h][s] = in[b][s][h]   (s=2048, h=1024)
// ---------------------------------------------------------------------------
__global__ void transpose_k(const bf16* __restrict__ in, bf16* __restrict__ out) {
    __shared__ bf16 t[32][33];
    const long long b = blockIdx.z;
    const bf16* ip = in  + b * 2048LL * 1024;
    bf16*       op = out + b * 2048LL * 1024;
    const int h0 = blockIdx.x * 32;
    const int s0 = blockIdx.y * 32;
    for (int i = threadIdx.y; i < 32; i += 8)
        t[i][threadIdx.x] = ip[(long long)(s0 + i) * 1024 + h0 + threadIdx.x];
    __syncthreads();
    for (int i = threadIdx.y; i < 32; i += 8)
        op[(long long)(h0 + i) * 2048 + s0 + threadIdx.x] = t[threadIdx.x][i];
}

// ---------------------------------------------------------------------------
// Row softmax over 2048 bf16, in place. One block (256 thr) per row.
// ---------------------------------------------------------------------------
__global__ void softmax_k(bf16* __restrict__ S) {
    const long long row = blockIdx.x;
    bf16* p = S + row * 2048;
    const int tid = threadIdx.x;

    uint4 u = reinterpret_cast<uint4*>(p)[tid];
    __nv_bfloat162* hp = reinterpret_cast<__nv_bfloat162*>(&u);
    float v[8];
#pragma unroll
    for (int i = 0; i < 4; ++i) {
        float2 f = __bfloat1622float2(hp[i]);
        v[2 * i] = f.x; v[2 * i + 1] = f.y;
    }
    float m = v[0];
#pragma unroll
    for (int i = 1; i < 8; ++i) m = fmaxf(m, v[i]);
#pragma unroll
    for (int o = 16; o > 0; o >>= 1) m = fmaxf(m, __shfl_xor_sync(0xffffffffu, m, o));
    __shared__ float red[8];
    if ((tid & 31) == 0) red[tid >> 5] = m;
    __syncthreads();
    float mm = red[0];
#pragma unroll
    for (int j = 1; j < 8; ++j) mm = fmaxf(mm, red[j]);

    float s = 0.f;
#pragma unroll
    for (int i = 0; i < 8; ++i) { v[i] = __expf(v[i] - mm); s += v[i]; }
#pragma unroll
    for (int o = 16; o > 0; o >>= 1) s += __shfl_xor_sync(0xffffffffu, s, o);
    __syncthreads();
    if ((tid & 31) == 0) red[tid >> 5] = s;
    __syncthreads();
    float ss = 0.f;
#pragma unroll
    for (int j = 0; j < 8; ++j) ss += red[j];
    const float inv = 1.0f / ss;

#pragma unroll
    for (int i = 0; i < 4; ++i)
        hp[i] = __floats2bfloat162_rn(v[2 * i] * inv, v[2 * i + 1] * inv);
    reinterpret_cast<uint4*>(p)[tid] = u;
}

// ---------------------------------------------------------------------------
// Row LayerNorm over 1024 fp32. One block (256 thr) per row.
// ---------------------------------------------------------------------------
__global__ void ln_k(const float* __restrict__ in, const float* __restrict__ gamma,
                     const float* __restrict__ beta, float* __restrict__ out) {
    const long long row = blockIdx.x;
    const int tid = threadIdx.x;
    const float4 v = reinterpret_cast<const float4*>(in + row * 1024)[tid];
    float s = v.x + v.y + v.z + v.w;
    float q = v.x * v.x + v.y * v.y + v.z * v.z + v.w * v.w;
#pragma unroll
    for (int o = 16; o > 0; o >>= 1) {
        s += __shfl_xor_sync(0xffffffffu, s, o);
        q += __shfl_xor_sync(0xffffffffu, q, o);
    }
    __shared__ float redS[8], redQ[8];
    if ((tid & 31) == 0) { redS[tid >> 5] = s; redQ[tid >> 5] = q; }
    __syncthreads();
    float S = 0.f, Q = 0.f;
#pragma unroll
    for (int j = 0; j < 8; ++j) { S += redS[j]; Q += redQ[j]; }
    const float mu  = S * (1.0f / 1024.0f);
    const float var = Q * (1.0f / 1024.0f) - mu * mu;
    const float rs  = rsqrtf(var + 1e-5f);
    const float4 g4 = reinterpret_cast<const float4*>(gamma)[tid];
    const float4 b4 = reinterpret_cast<const float4*>(beta)[tid];
    float4 o;
    o.x = (v.x - mu) * rs * g4.x + b4.x;
    o.y = (v.y - mu) * rs * g4.y + b4.y;
    o.z = (v.z - mu) * rs * g4.z + b4.z;
    o.w = (v.w - mu) * rs * g4.w + b4.w;
    reinterpret_cast<float4*>(out + row * 1024)[tid] = o;
}

// ---------------------------------------------------------------------------
// NT GEMM on mma.sync tensor cores (bf16 in, fp32 accum):
//   C[z][m][n] (+epi) = sum_k A[z][m][k] * B[z][n][k]
// Block tile 256x128x32, 8 warps (4x2), warp tile 64x64 (4x8 m16n8k16),
// 4-stage cp.async pipeline, padded smem (row stride 40 bf16 = 80B,
// conflict-free for ldmatrix and 16B-aligned for cp.async).
// MODE 0: +bias -> bf16 | 1: *scale -> bf16 | 2: plain -> bf16
// MODE 3: +bias +fp32 residual -> fp32
// ---------------------------------------------------------------------------
#define BM 256
#define BN 128
#define BK 32
#define NS 4
#define SAPAD 40
#define A_STAGE_B (BM * SAPAD * 2)            // 20480 B
#define B_STAGE_B (BN * SAPAD * 2)            // 10240 B
#define STAGE_B   (A_STAGE_B + B_STAGE_B)     // 30720 B
#define SMEM_DYN  (NS * STAGE_B)              // 122880 B

__device__ __forceinline__ void load_stage(uint32_t sbase,
                                           const bf16* __restrict__ Ab, int lda,
                                           const bf16* __restrict__ Bb, int ldb,
                                           int k0, int tid) {
    // A: 256 rows x 4 chunks of 16B
#pragma unroll
    for (int i = 0; i < 4; ++i) {
        const int idx = tid + i * 256;
        const int r = idx >> 2, c = idx & 3;
        const uint32_t dst = sbase + (uint32_t)(r * (SAPAD * 2) + c * 16);
        const bf16* src = Ab + (long long)r * lda + (k0 + c * 8);
        asm volatile("cp.async.cg.shared.global [%0], [%1], 16;\n" :: "r"(dst), "l"(src));
    }
    // B: 128 rows x 4 chunks of 16B
#pragma unroll
    for (int i = 0; i < 2; ++i) {
        const int idx = tid + i * 256;
        const int r = idx >> 2, c = idx & 3;
        const uint32_t dst = sbase + A_STAGE_B + (uint32_t)(r * (SAPAD * 2) + c * 16);
        const bf16* src = Bb + (long long)r * ldb + (k0 + c * 8);
        asm volatile("cp.async.cg.shared.global [%0], [%1], 16;\n" :: "r"(dst), "l"(src));
    }
    asm volatile("cp.async.commit_group;\n");
}

template <int MODE>
__global__ __launch_bounds__(256, 1) void gemm_nt(
    const bf16* __restrict__ A, int lda, long long sAz,
    const bf16* __restrict__ Bm, int ldb, long long sBz,
    void* __restrict__ Cv, int ldc, long long sCz,
    int K,
    const float* __restrict__ bias,
    const float* __restrict__ resid, int ldr,
    float scale) {
    extern __shared__ __align__(16) char dynsmem[];

    const int tid  = threadIdx.x;
    const int lane = tid & 31;
    const int warp = tid >> 5;
    const int wm   = warp >> 1;   // 0..3  (64 rows each)
    const int wn   = warp & 1;    // 0..1  (64 cols each)
    const long long z = blockIdx.z;

    const bf16* Ab = A  + z * sAz + (long long)blockIdx.y * BM * lda;
    const bf16* Bb = Bm + z * sBz + (long long)blockIdx.x * BN * ldb;

    const uint32_t sbase = (uint32_t)__cvta_generic_to_shared(dynsmem);

    float acc[4][8][4];
#pragma unroll
    for (int a = 0; a < 4; ++a)
#pragma unroll
        for (int b = 0; b < 8; ++b)
#pragma unroll
            for (int c = 0; c < 4; ++c) acc[a][b][c] = 0.f;

    const int T = K >> 5;   // BK = 32

    // prologue: stages 0..NS-2
#pragma unroll
    for (int s = 0; s < NS - 1; ++s)
        load_stage(sbase + s * STAGE_B, Ab, lda, Bb, ldb, s * BK, tid);

    for (int t = 0; t < T; ++t) {
        asm volatile("cp.async.wait_group %0;\n" :: "n"(NS - 2) : "memory");
        __syncthreads();

        // issue load for stage t+NS-1 into the buffer freed at end of iter t-1
        const int lt = t + NS - 1;
        if (lt < T)
            load_stage(sbase + (lt % NS) * STAGE_B, Ab, lda, Bb, ldb, lt * BK, tid);
        else
            asm volatile("cp.async.commit_group;\n");   // keep group count aligned

        const uint32_t aB = sbase + (t % NS) * STAGE_B;
        const uint32_t bB = aB + A_STAGE_B;
#pragma unroll
        for (int ks = 0; ks < 2; ++ks) {
            const int kb = ks * 16;
            uint32_t af[4][4];
#pragma unroll
            for (int mt = 0; mt < 4; ++mt) {
                const int row = wm * 64 + mt * 16 + (lane & 7) + ((lane >> 3) & 1) * 8;
                const int col = kb + ((lane >> 4) << 3);
                const uint32_t ad = aB + (uint32_t)(row * (SAPAD * 2) + col * 2);
                asm volatile(
                    "ldmatrix.sync.aligned.m8n8.x4.shared.b16 {%0,%1,%2,%3}, [%4];"
                    : "=r"(af[mt][0]), "=r"(af[mt][1]), "=r"(af[mt][2]), "=r"(af[mt][3])
                    : "r"(ad));
            }
            uint32_t bfr[8][2];
#pragma unroll
            for (int np = 0; np < 4; ++np) {
                const int row = wn * 64 + np * 16 + (lane & 15);
                const int col = kb + ((lane >> 4) << 3);
                const uint32_t bd = bB + (uint32_t)(row * (SAPAD * 2) + col * 2);
                uint32_t r0, r1, r2, r3;
                asm volatile(
                    "ldmatrix.sync.aligned.m8n8.x4.shared.b16 {%0,%1,%2,%3}, [%4];"
                    : "=r"(r0), "=r"(r1), "=r"(r2), "=r"(r3)
                    : "r"(bd));
                bfr[2 * np][0]     = r0; bfr[2 * np][1]     = r2;
                bfr[2 * np + 1][0] = r1; bfr[2 * np + 1][1] = r3;
            }
#pragma unroll
            for (int mt = 0; mt < 4; ++mt)
#pragma unroll
                for (int nt = 0; nt < 8; ++nt)
                    asm volatile(
                        "mma.sync.aligned.m16n8k16.row.col.f32.bf16.bf16.f32 "
                        "{%0,%1,%2,%3}, {%4,%5,%6,%7}, {%8,%9}, {%0,%1,%2,%3};"
                        : "+f"(acc[mt][nt][0]), "+f"(acc[mt][nt][1]),
                          "+f"(acc[mt][nt][2]), "+f"(acc[mt][nt][3])
                        : "r"(af[mt][0]), "r"(af[mt][1]), "r"(af[mt][2]), "r"(af[mt][3]),
                          "r"(bfr[nt][0]), "r"(bfr[nt][1]));
        }
        __syncthreads();
    }

    // Epilogue. acc[.][.][0]=(r0,c0) [1]=(r0,c0+1) [2]=(r0+8,c0) [3]=(r0+8,c0+1)
    const int g  = lane >> 2;
    const int tq = lane & 3;
    const int rbase = blockIdx.y * BM + wm * 64;
    const int cbase = blockIdx.x * BN + wn * 64;
#pragma unroll
    for (int mt = 0; mt < 4; ++mt) {
#pragma unroll
        for (int nt = 0; nt < 8; ++nt) {
            const int r0 = rbase + mt * 16 + g;
            const int c0 = cbase + nt * 8 + 2 * tq;
            float v00 = acc[mt][nt][0], v01 = acc[mt][nt][1];
            float v10 = acc[mt][nt][2], v11 = acc[mt][nt][3];
            if (MODE == 1) { v00 *= scale; v01 *= scale; v10 *= scale; v11 *= scale; }
            if (MODE == 0 || MODE == 3) {
                const float b0 = bias[c0], b1 = bias[c0 + 1];
                v00 += b0; v01 += b1; v10 += b0; v11 += b1;
            }
            if (MODE == 3) {
                float* Cf = (float*)Cv + z * sCz;
                const long long i0 = (long long)r0 * ldc + c0;
                const long long i1 = (long long)(r0 + 8) * ldc + c0;
                const float2 ra = reinterpret_cast<const float2*>(resid + (long long)r0 * ldr + c0)[0];
                const float2 rb = reinterpret_cast<const float2*>(resid + (long long)(r0 + 8) * ldr + c0)[0];
                reinterpret_cast<float2*>(Cf + i0)[0] = make_float2(v00 + ra.x, v01 + ra.y);
                reinterpret_cast<float2*>(Cf + i1)[0] = make_float2(v10 + rb.x, v11 + rb.y);
            } else {
                bf16* Cb = (bf16*)Cv + z * sCz;
                reinterpret_cast<__nv_bfloat162*>(Cb + (long long)r0 * ldc + c0)[0] =
                    __floats2bfloat162_rn(v00, v01);
                reinterpret_cast<__nv_bfloat162*>(Cb + (long long)(r0 + 8) * ldc + c0)[0] =
                    __floats2bfloat162_rn(v10, v11);
            }
        }
    }
}

// ---------------------------------------------------------------------------
// Host orchestration
// ---------------------------------------------------------------------------
extern "C" void kernel_launch(void* const* d_in, const int* in_sizes, int n_in,
                              void* d_out, int out_size) {
    (void)in_sizes; (void)n_in; (void)out_size;
    const float* x     = (const float*)d_in[0];
    const float* Wq    = (const float*)d_in[1];
    const float* bq    = (const float*)d_in[2];
    const float* Wk    = (const float*)d_in[3];
    const float* bk    = (const float*)d_in[4];
    const float* Wv    = (const float*)d_in[5];
    const float* bv    = (const float*)d_in[6];
    const float* Wo    = (const float*)d_in[7];
    const float* bo    = (const float*)d_in[8];
    const float* gamma = (const float*)d_in[9];
    const float* beta  = (const float*)d_in[10];

    void* p;
    bf16 *xb, *wq, *wk, *wv, *wo, *qb, *kb, *vb, *vtb, *sb, *wtb;
    float* pre;
    cudaGetSymbolAddress(&p, g_xb);  xb  = (bf16*)p;
    cudaGetSymbolAddress(&p, g_wq);  wq  = (bf16*)p;
    cudaGetSymbolAddress(&p, g_wk);  wk  = (bf16*)p;
    cudaGetSymbolAddress(&p, g_wv);  wv  = (bf16*)p;
    cudaGetSymbolAddress(&p, g_wo);  wo  = (bf16*)p;
    cudaGetSymbolAddress(&p, g_q);   qb  = (bf16*)p;
    cudaGetSymbolAddress(&p, g_k);   kb  = (bf16*)p;
    cudaGetSymbolAddress(&p, g_v);   vb  = (bf16*)p;
    cudaGetSymbolAddress(&p, g_vt);  vtb = (bf16*)p;
    cudaGetSymbolAddress(&p, g_s);   sb  = (bf16*)p;
    cudaGetSymbolAddress(&p, g_w);   wtb = (bf16*)p;
    cudaGetSymbolAddress(&p, g_pre); pre = (float*)p;

    cudaFuncSetAttribute(gemm_nt<0>, cudaFuncAttributeMaxDynamicSharedMemorySize, SMEM_DYN);
    cudaFuncSetAttribute(gemm_nt<1>, cudaFuncAttributeMaxDynamicSharedMemorySize, SMEM_DYN);
    cudaFuncSetAttribute(gemm_nt<2>, cudaFuncAttributeMaxDynamicSharedMemorySize, SMEM_DYN);
    cudaFuncSetAttribute(gemm_nt<3>, cudaFuncAttributeMaxDynamicSharedMemorySize, SMEM_DYN);

    // 1) fp32 -> bf16 conversions (vectorized)
    cvt_k<<<2048, 256>>>((const float4*)x,  (uint2*)xb, 16384 * 256);
    cvt_k<<<512,  256>>>((const float4*)Wq, (uint2*)wq, 1024 * 256);
    cvt_k<<<512,  256>>>((const float4*)Wk, (uint2*)wk, 1024 * 256);
    cvt_k<<<512,  256>>>((const float4*)Wv, (uint2*)wv, 1024 * 256);
    cvt_k<<<512,  256>>>((const float4*)Wo, (uint2*)wo, 1024 * 256);

    const dim3 blk(256);

    // 2) QKV projections: [16384,1024] = x @ W^T + b
    const dim3 gQKV(1024 / BN, 16384 / BM, 1);
    gemm_nt<0><<<gQKV, blk, SMEM_DYN>>>(xb, 1024, 0, wq, 1024, 0, qb, 1024, 0, 1024, bq, nullptr, 0, 0.f);
    gemm_nt<0><<<gQKV, blk, SMEM_DYN>>>(xb, 1024, 0, wk, 1024, 0, kb, 1024, 0, 1024, bk, nullptr, 0, 0.f);
    gemm_nt<0><<<gQKV, blk, SMEM_DYN>>>(xb, 1024, 0, wv, 1024, 0, vb, 1024, 0, 1024, bv, nullptr, 0, 0.f);

    // 3) V -> V^T per batch
    transpose_k<<<dim3(1024 / 32, 2048 / 32, 8), dim3(32, 8)>>>(vb, vtb);

    // 4) scores[b] = (Q[b] @ K[b]^T) * 1/sqrt(1024)
    const dim3 gS(2048 / BN, 2048 / BM, 8);
    gemm_nt<1><<<gS, blk, SMEM_DYN>>>(qb, 1024, 2048LL * 1024, kb, 1024, 2048LL * 1024,
                                      sb, 2048, 2048LL * 2048, 1024, nullptr, nullptr, 0, 0.03125f);

    // 5) softmax rows (in place, fp32 math)
    softmax_k<<<16384, 256>>>(sb);

    // 6) weighted[b] = attn[b] @ V[b]   (NT against V^T)
    const dim3 gW(1024 / BN, 2048 / BM, 8);
    gemm_nt<2><<<gW, blk, SMEM_DYN>>>(sb, 2048, 2048LL * 2048, vtb, 2048, 1024LL * 2048,
                                      wtb, 1024, 2048LL * 1024, 2048, nullptr, nullptr, 0, 0.f);

    // 7) pre = weighted @ Wo^T + bo + x   (fp32 residual, fp32 out)
    gemm_nt<3><<<gQKV, blk, SMEM_DYN>>>(wtb, 1024, 0, wo, 1024, 0, pre, 1024, 0, 1024, bo, x, 1024, 0.f);

    // 8) LayerNorm -> d_out
    ln_k<<<16384, 256>>>(pre, gamma, beta, (float*)d_out);
}

// round 12
// speedup vs baseline: 1.2851x; 1.2851x over previous
#include <cuda_runtime.h>
#include <cuda_bf16.h>
#include <cstdint>
#include <math.h>

using bf16 = __nv_bfloat16;

// B=8, S=2048, D=1024
// ---------------------------------------------------------------------------
// Device scratch (allocation-free rule: __device__ globals)
// ---------------------------------------------------------------------------
__device__ __align__(16) bf16  g_xb  [16384LL*1024];
__device__ __align__(16) bf16  g_wqkv[3072LL*1024];    // Wq|Wk|Wv rows
__device__ __align__(16) float g_bqkv[3072];
__device__ __align__(16) bf16  g_wo  [1024LL*1024];
__device__ __align__(16) bf16  g_qkv [16384LL*3072];   // Q|K|V columns
__device__ __align__(16) bf16  g_vt  [8LL*1024*2048];  // [b][h][s]
__device__ __align__(16) bf16  g_s   [8LL*2048*2048];  // scores / attn
__device__ __align__(16) bf16  g_w   [16384LL*1024];   // weighted
__device__ __align__(16) float g_pre [16384LL*1024];   // pre-LayerNorm

// ---------------------------------------------------------------------------
// fp32 -> bf16 convert (vectorized)
// ---------------------------------------------------------------------------
__global__ void cvt_k(const float4* __restrict__ in, uint2* __restrict__ out, int n4) {
    for (int i = blockIdx.x * blockDim.x + threadIdx.x; i < n4;
         i += gridDim.x * blockDim.x) {
        float4 f = in[i];
        uint2 o;
        __nv_bfloat162 lo = __floats2bfloat162_rn(f.x, f.y);
        __nv_bfloat162 hi = __floats2bfloat162_rn(f.z, f.w);
        o.x = *reinterpret_cast<uint32_t*>(&lo);
        o.y = *reinterpret_cast<uint32_t*>(&hi);
        out[i] = o;
    }
}

// concat 3 bias vectors [1024] -> [3072]
__global__ void bcat_k(const float* __restrict__ a, const float* __restrict__ b,
                       const float* __restrict__ c, float* __restrict__ o) {
    const int i = blockIdx.x * blockDim.x + threadIdx.x;   // 0..1023
    o[i] = a[i]; o[i + 1024] = b[i]; o[i + 2048] = c[i];
}

// ---------------------------------------------------------------------------
// Per-batch transpose: out[b][h][s] = in[b][s][h]  (in = V slice, stride 3072)
// ---------------------------------------------------------------------------
__global__ void transpose_k(const bf16* __restrict__ in, bf16* __restrict__ out) {
    __shared__ bf16 t[32][33];
    const long long b = blockIdx.z;
    const bf16* ip = in  + b * 2048LL * 3072;
    bf16*       op = out + b * 2048LL * 1024;
    const int h0 = blockIdx.x * 32;
    const int s0 = blockIdx.y * 32;
    for (int i = threadIdx.y; i < 32; i += 8)
        t[i][threadIdx.x] = ip[(long long)(s0 + i) * 3072 + h0 + threadIdx.x];
    __syncthreads();
    for (int i = threadIdx.y; i < 32; i += 8)
        op[(long long)(h0 + i) * 2048 + s0 + threadIdx.x] = t[threadIdx.x][i];
}

// ---------------------------------------------------------------------------
// Row softmax over 2048 bf16, in place. One block (256 thr) per row.
// ---------------------------------------------------------------------------
__global__ void softmax_k(bf16* __restrict__ S) {
    const long long row = blockIdx.x;
    bf16* p = S + row * 2048;
    const int tid = threadIdx.x;

    uint4 u = reinterpret_cast<uint4*>(p)[tid];
    __nv_bfloat162* hp = reinterpret_cast<__nv_bfloat162*>(&u);
    float v[8];
#pragma unroll
    for (int i = 0; i < 4; ++i) {
        float2 f = __bfloat1622float2(hp[i]);
        v[2 * i] = f.x; v[2 * i + 1] = f.y;
    }
    float m = v[0];
#pragma unroll
    for (int i = 1; i < 8; ++i) m = fmaxf(m, v[i]);
#pragma unroll
    for (int o = 16; o > 0; o >>= 1) m = fmaxf(m, __shfl_xor_sync(0xffffffffu, m, o));
    __shared__ float red[8];
    if ((tid & 31) == 0) red[tid >> 5] = m;
    __syncthreads();
    float mm = red[0];
#pragma unroll
    for (int j = 1; j < 8; ++j) mm = fmaxf(mm, red[j]);

    float s = 0.f;
#pragma unroll
    for (int i = 0; i < 8; ++i) { v[i] = __expf(v[i] - mm); s += v[i]; }
#pragma unroll
    for (int o = 16; o > 0; o >>= 1) s += __shfl_xor_sync(0xffffffffu, s, o);
    __syncthreads();
    if ((tid & 31) == 0) red[tid >> 5] = s;
    __syncthreads();
    float ss = 0.f;
#pragma unroll
    for (int j = 0; j < 8; ++j) ss += red[j];
    const float inv = 1.0f / ss;

#pragma unroll
    for (int i = 0; i < 4; ++i)
        hp[i] = __floats2bfloat162_rn(v[2 * i] * inv, v[2 * i + 1] * inv);
    reinterpret_cast<uint4*>(p)[tid] = u;
}

// ---------------------------------------------------------------------------
// Row LayerNorm over 1024 fp32. One block (256 thr) per row.
// ---------------------------------------------------------------------------
__global__ void ln_k(const float* __restrict__ in, const float* __restrict__ gamma,
                     const float* __restrict__ beta, float* __restrict__ out) {
    const long long row = blockIdx.x;
    const int tid = threadIdx.x;
    const float4 v = reinterpret_cast<const float4*>(in + row * 1024)[tid];
    float s = v.x + v.y + v.z + v.w;
    float q = v.x * v.x + v.y * v.y + v.z * v.z + v.w * v.w;
#pragma unroll
    for (int o = 16; o > 0; o >>= 1) {
        s += __shfl_xor_sync(0xffffffffu, s, o);
        q += __shfl_xor_sync(0xffffffffu, q, o);
    }
    __shared__ float redS[8], redQ[8];
    if ((tid & 31) == 0) { redS[tid >> 5] = s; redQ[tid >> 5] = q; }
    __syncthreads();
    float S = 0.f, Q = 0.f;
#pragma unroll
    for (int j = 0; j < 8; ++j) { S += redS[j]; Q += redQ[j]; }
    const float mu  = S * (1.0f / 1024.0f);
    const float var = Q * (1.0f / 1024.0f) - mu * mu;
    const float rs  = rsqrtf(var + 1e-5f);
    const float4 g4 = reinterpret_cast<const float4*>(gamma)[tid];
    const float4 b4 = reinterpret_cast<const float4*>(beta)[tid];
    float4 o;
    o.x = (v.x - mu) * rs * g4.x + b4.x;
    o.y = (v.y - mu) * rs * g4.y + b4.y;
    o.z = (v.z - mu) * rs * g4.z + b4.z;
    o.w = (v.w - mu) * rs * g4.w + b4.w;
    reinterpret_cast<float4*>(out + row * 1024)[tid] = o;
}

// ---------------------------------------------------------------------------
// NT GEMM on mma.sync tensor cores (bf16 in, fp32 accum):
//   C[z][m][n] (+epi) = sum_k A[z][m][k] * B[z][n][k]
// Block tile 128x128x32, 8 warps (2x4), warp tile 64x32 (4x4 m16n8k16),
// 3-stage cp.async pipeline, ONE syncthreads per k-tile, x4 ldmatrix for A+B,
// padded smem (row stride 40 bf16), __launch_bounds__(256,2) -> 2 CTAs/SM.
// MODE 0: +bias -> bf16 | 1: *scale -> bf16 | 2: plain -> bf16
// MODE 3: +bias +fp32 residual -> fp32
// ---------------------------------------------------------------------------
#define BM 128
#define BN 128
#define BK 32
#define NS 3
#define SAPAD 40
#define TILE_B  (128 * SAPAD * 2)            // 10240 B (one operand, one stage)
#define STAGE_B (2 * TILE_B)                 // 20480 B
#define SMEM_DYN (NS * STAGE_B)              // 61440 B

__device__ __forceinline__ void load_stage(uint32_t sbase,
                                           const bf16* __restrict__ Ab, int lda,
                                           const bf16* __restrict__ Bb, int ldb,
                                           int k0, int tid) {
    // A: 128 rows x 4 chunks of 16B = 512 ops / 256 thr
#pragma unroll
    for (int i = 0; i < 2; ++i) {
        const int idx = tid + i * 256;
        const int r = idx >> 2, c = idx & 3;
        const uint32_t dst = sbase + (uint32_t)(r * (SAPAD * 2) + c * 16);
        const bf16* src = Ab + (long long)r * lda + (k0 + c * 8);
        asm volatile("cp.async.cg.shared.global [%0], [%1], 16;\n" :: "r"(dst), "l"(src));
    }
    // B
#pragma unroll
    for (int i = 0; i < 2; ++i) {
        const int idx = tid + i * 256;
        const int r = idx >> 2, c = idx & 3;
        const uint32_t dst = sbase + TILE_B + (uint32_t)(r * (SAPAD * 2) + c * 16);
        const bf16* src = Bb + (long long)r * ldb + (k0 + c * 8);
        asm volatile("cp.async.cg.shared.global [%0], [%1], 16;\n" :: "r"(dst), "l"(src));
    }
    asm volatile("cp.async.commit_group;\n");
}

template <int MODE>
__global__ __launch_bounds__(256, 2) void gemm_nt(
    const bf16* __restrict__ A, int lda, long long sAz,
    const bf16* __restrict__ Bm, int ldb, long long sBz,
    void* __restrict__ Cv, int ldc, long long sCz,
    int K,
    const float* __restrict__ bias,
    const float* __restrict__ resid, int ldr,
    float scale) {
    extern __shared__ __align__(16) char dynsmem[];

    const int tid  = threadIdx.x;
    const int lane = tid & 31;
    const int warp = tid >> 5;
    const int wm   = warp >> 2;   // 0..1  (64 rows each)
    const int wn   = warp & 3;    // 0..3  (32 cols each)
    const long long z = blockIdx.z;

    const bf16* Ab = A  + z * sAz + (long long)blockIdx.y * BM * lda;
    const bf16* Bb = Bm + z * sBz + (long long)blockIdx.x * BN * ldb;

    const uint32_t sbase = (uint32_t)__cvta_generic_to_shared(dynsmem);

    float acc[4][4][4];
#pragma unroll
    for (int a = 0; a < 4; ++a)
#pragma unroll
        for (int b = 0; b < 4; ++b)
#pragma unroll
            for (int c = 0; c < 4; ++c) acc[a][b][c] = 0.f;

    const int T = K >> 5;   // BK = 32

    // prologue: stages 0..NS-2
#pragma unroll
    for (int s = 0; s < NS - 1; ++s)
        load_stage(sbase + s * STAGE_B, Ab, lda, Bb, ldb, s * BK, tid);

    // precomputed smem read offsets
    const uint32_t a_off = (uint32_t)(((lane & 7) + ((lane >> 3) & 1) * 8) * (SAPAD * 2)
                                      + ((lane >> 4) << 3) * 2);
    // B x4: grp = lane>>3 : mat0=(n0-7,k0-7) mat1=(n0-7,k8-15) mat2=(n8-15,k0-7) mat3=(n8-15,k8-15)
    const int bgrp = lane >> 3, brr = lane & 7;
    const uint32_t b_off = (uint32_t)((((bgrp >> 1) & 1) * 8 + brr) * (SAPAD * 2)
                                      + ((bgrp & 1) * 8) * 2);

    for (int t = 0; t < T; ++t) {
        asm volatile("cp.async.wait_group %0;\n" :: "n"(NS - 2) : "memory");
        __syncthreads();   // single rendezvous: data of stage t visible, stage t-1 reads done

        const int lt = t + NS - 1;
        if (lt < T)
            load_stage(sbase + (lt % NS) * STAGE_B, Ab, lda, Bb, ldb, lt * BK, tid);
        else
            asm volatile("cp.async.commit_group;\n");

        const uint32_t aB = sbase + (t % NS) * STAGE_B + wm * 64 * (SAPAD * 2) + a_off;
        const uint32_t bB = sbase + (t % NS) * STAGE_B + TILE_B + wn * 32 * (SAPAD * 2) + b_off;
#pragma unroll
        for (int ks = 0; ks < 2; ++ks) {
            const uint32_t kboff = (uint32_t)(ks * 16 * 2);
            uint32_t af[4][4];
#pragma unroll
            for (int mt = 0; mt < 4; ++mt) {
                const uint32_t ad = aB + mt * 16 * (SAPAD * 2) + kboff;
                asm volatile(
                    "ldmatrix.sync.aligned.m8n8.x4.shared.b16 {%0,%1,%2,%3}, [%4];"
                    : "=r"(af[mt][0]), "=r"(af[mt][1]), "=r"(af[mt][2]), "=r"(af[mt][3])
                    : "r"(ad));
            }
            uint32_t bfr[4][2];
#pragma unroll
            for (int np = 0; np < 2; ++np) {
                const uint32_t bd = bB + np * 16 * (SAPAD * 2) + kboff;
                uint32_t r0, r1, r2, r3;
                asm volatile(
                    "ldmatrix.sync.aligned.m8n8.x4.shared.b16 {%0,%1,%2,%3}, [%4];"
                    : "=r"(r0), "=r"(r1), "=r"(r2), "=r"(r3)
                    : "r"(bd));
                bfr[2 * np][0]     = r0; bfr[2 * np][1]     = r1;
                bfr[2 * np + 1][0] = r2; bfr[2 * np + 1][1] = r3;
            }
#pragma unroll
            for (int mt = 0; mt < 4; ++mt)
#pragma unroll
                for (int nt = 0; nt < 4; ++nt)
                    asm volatile(
                        "mma.sync.aligned.m16n8k16.row.col.f32.bf16.bf16.f32 "
                        "{%0,%1,%2,%3}, {%4,%5,%6,%7}, {%8,%9}, {%0,%1,%2,%3};"
                        : "+f"(acc[mt][nt][0]), "+f"(acc[mt][nt][1]),
                          "+f"(acc[mt][nt][2]), "+f"(acc[mt][nt][3])
                        : "r"(af[mt][0]), "r"(af[mt][1]), "r"(af[mt][2]), "r"(af[mt][3]),
                          "r"(bfr[nt][0]), "r"(bfr[nt][1]));
        }
    }

    // Epilogue. acc[.][.][0]=(r0,c0) [1]=(r0,c0+1) [2]=(r0+8,c0) [3]=(r0+8,c0+1)
    const int g  = lane >> 2;
    const int tq = lane & 3;
    const int rbase = blockIdx.y * BM + wm * 64;
    const int cbase = blockIdx.x * BN + wn * 32;
#pragma unroll
    for (int mt = 0; mt < 4; ++mt) {
#pragma unroll
        for (int nt = 0; nt < 4; ++nt) {
            const int r0 = rbase + mt * 16 + g;
            const int c0 = cbase + nt * 8 + 2 * tq;
            float v00 = acc[mt][nt][0], v01 = acc[mt][nt][1];
            float v10 = acc[mt][nt][2], v11 = acc[mt][nt][3];
            if (MODE == 1) { v00 *= scale; v01 *= scale; v10 *= scale; v11 *= scale; }
            if (MODE == 0 || MODE == 3) {
                const float b0 = bias[c0], b1 = bias[c0 + 1];
                v00 += b0; v01 += b1; v10 += b0; v11 += b1;
            }
            if (MODE == 3) {
                float* Cf = (float*)Cv + z * sCz;
                const long long i0 = (long long)r0 * ldc + c0;
                const long long i1 = (long long)(r0 + 8) * ldc + c0;
                const float2 ra = reinterpret_cast<const float2*>(resid + (long long)r0 * ldr + c0)[0];
                const float2 rb = reinterpret_cast<const float2*>(resid + (long long)(r0 + 8) * ldr + c0)[0];
                reinterpret_cast<float2*>(Cf + i0)[0] = make_float2(v00 + ra.x, v01 + ra.y);
                reinterpret_cast<float2*>(Cf + i1)[0] = make_float2(v10 + rb.x, v11 + rb.y);
            } else {
                bf16* Cb = (bf16*)Cv + z * sCz;
                reinterpret_cast<__nv_bfloat162*>(Cb + (long long)r0 * ldc + c0)[0] =
                    __floats2bfloat162_rn(v00, v01);
                reinterpret_cast<__nv_bfloat162*>(Cb + (long long)(r0 + 8) * ldc + c0)[0] =
                    __floats2bfloat162_rn(v10, v11);
            }
        }
    }
}

// ---------------------------------------------------------------------------
// Host orchestration
// ---------------------------------------------------------------------------
extern "C" void kernel_launch(void* const* d_in, const int* in_sizes, int n_in,
                              void* d_out, int out_size) {
    (void)in_sizes; (void)n_in; (void)out_size;
    const float* x     = (const float*)d_in[0];
    const float* Wq    = (const float*)d_in[1];
    const float* bq    = (const float*)d_in[2];
    const float* Wk    = (const float*)d_in[3];
    const float* bk    = (const float*)d_in[4];
    const float* Wv    = (const float*)d_in[5];
    const float* bv    = (const float*)d_in[6];
    const float* Wo    = (const float*)d_in[7];
    const float* bo    = (const float*)d_in[8];
    const float* gamma = (const float*)d_in[9];
    const float* beta  = (const float*)d_in[10];

    void* p;
    bf16 *xb, *wqkv, *wo, *qkv, *vtb, *sb, *wtb;
    float *bqkv, *pre;
    cudaGetSymbolAddress(&p, g_xb);   xb   = (bf16*)p;
    cudaGetSymbolAddress(&p, g_wqkv); wqkv = (bf16*)p;
    cudaGetSymbolAddress(&p, g_bqkv); bqkv = (float*)p;
    cudaGetSymbolAddress(&p, g_wo);   wo   = (bf16*)p;
    cudaGetSymbolAddress(&p, g_qkv);  qkv  = (bf16*)p;
    cudaGetSymbolAddress(&p, g_vt);   vtb  = (bf16*)p;
    cudaGetSymbolAddress(&p, g_s);    sb   = (bf16*)p;
    cudaGetSymbolAddress(&p, g_w);    wtb  = (bf16*)p;
    cudaGetSymbolAddress(&p, g_pre);  pre  = (float*)p;

    cudaFuncSetAttribute(gemm_nt<0>, cudaFuncAttributeMaxDynamicSharedMemorySize, SMEM_DYN);
    cudaFuncSetAttribute(gemm_nt<1>, cudaFuncAttributeMaxDynamicSharedMemorySize, SMEM_DYN);
    cudaFuncSetAttribute(gemm_nt<2>, cudaFuncAttributeMaxDynamicSharedMemorySize, SMEM_DYN);
    cudaFuncSetAttribute(gemm_nt<3>, cudaFuncAttributeMaxDynamicSharedMemorySize, SMEM_DYN);

    // 1) fp32 -> bf16 conversions; weights go into concatenated W_qkv
    cvt_k<<<2048, 256>>>((const float4*)x,  (uint2*)xb,               16384 * 256);
    cvt_k<<<512,  256>>>((const float4*)Wq, (uint2*)(wqkv),           1024 * 256);
    cvt_k<<<512,  256>>>((const float4*)Wk, (uint2*)(wqkv + 1024LL*1024), 1024 * 256);
    cvt_k<<<512,  256>>>((const float4*)Wv, (uint2*)(wqkv + 2048LL*1024), 1024 * 256);
    cvt_k<<<512,  256>>>((const float4*)Wo, (uint2*)wo,               1024 * 256);
    bcat_k<<<4, 256>>>(bq, bk, bv, bqkv);

    const dim3 blk(256);

    // 2) fused QKV: [16384,3072] = x @ [Wq|Wk|Wv]^T + b
    const dim3 gQKV(3072 / BN, 16384 / BM, 1);
    gemm_nt<0><<<gQKV, blk, SMEM_DYN>>>(xb, 1024, 0, wqkv, 1024, 0,
                                        qkv, 3072, 0, 1024, bqkv, nullptr, 0, 0.f);

    // 3) V -> V^T per batch (V = qkv cols 2048..3071)
    transpose_k<<<dim3(1024 / 32, 2048 / 32, 8), dim3(32, 8)>>>(qkv + 2048, vtb);

    // 4) scores[b] = (Q[b] @ K[b]^T) * 1/sqrt(1024)
    const dim3 gS(2048 / BN, 2048 / BM, 8);
    gemm_nt<1><<<gS, blk, SMEM_DYN>>>(qkv,        3072, 2048LL * 3072,
                                      qkv + 1024, 3072, 2048LL * 3072,
                                      sb, 2048, 2048LL * 2048, 1024,
                                      nullptr, nullptr, 0, 0.03125f);

    // 5) softmax rows (in place, fp32 math)
    softmax_k<<<16384, 256>>>(sb);

    // 6) weighted[b] = attn[b] @ V[b]   (NT against V^T)
    const dim3 gW(1024 / BN, 2048 / BM, 8);
    gemm_nt<2><<<gW, blk, SMEM_DYN>>>(sb, 2048, 2048LL * 2048, vtb, 2048, 1024LL * 2048,
                                      wtb, 1024, 2048LL * 1024, 2048, nullptr, nullptr, 0, 0.f);

    // 7) pre = weighted @ Wo^T + bo + x   (fp32 residual, fp32 out)
    const dim3 gO(1024 / BN, 16384 / BM, 1);
    gemm_nt<3><<<gO, blk, SMEM_DYN>>>(wtb, 1024, 0, wo, 1024, 0, pre, 1024, 0, 1024, bo, x, 1024, 0.f);

    // 8) LayerNorm -> d_out
    ln_k<<<16384, 256>>>(pre, gamma, beta, (float*)d_out);
}

// round 13
// speedup vs baseline: 1.4310x; 1.1135x over previous
#include <cuda_runtime.h>
#include <cuda_bf16.h>
#include <cstdint>
#include <math.h>

using bf16 = __nv_bfloat16;

// B=8, S=2048, D=1024
// ---------------------------------------------------------------------------
// Device scratch (allocation-free rule: __device__ globals)
// ---------------------------------------------------------------------------
__device__ __align__(16) bf16  g_xb  [16384LL*1024];
__device__ __align__(16) bf16  g_wqkv[3072LL*1024];    // Wq|Wk|Wv rows
__device__ __align__(16) float g_bqkv[3072];
__device__ __align__(16) bf16  g_wo  [1024LL*1024];
__device__ __align__(16) bf16  g_qkv [16384LL*3072];   // Q|K|V columns
__device__ __align__(16) bf16  g_vt  [8LL*1024*2048];  // [b][h][s]
__device__ __align__(16) bf16  g_s   [8LL*2048*2048];  // scores / attn
__device__ __align__(16) bf16  g_w   [16384LL*1024];   // weighted
__device__ __align__(16) float g_pre [16384LL*1024];   // pre-LayerNorm

// ---------------------------------------------------------------------------
// fp32 -> bf16 convert (vectorized)
// ---------------------------------------------------------------------------
__global__ void cvt_k(const float4* __restrict__ in, uint2* __restrict__ out, int n4) {
    for (int i = blockIdx.x * blockDim.x + threadIdx.x; i < n4;
         i += gridDim.x * blockDim.x) {
        float4 f = in[i];
        uint2 o;
        __nv_bfloat162 lo = __floats2bfloat162_rn(f.x, f.y);
        __nv_bfloat162 hi = __floats2bfloat162_rn(f.z, f.w);
        o.x = *reinterpret_cast<uint32_t*>(&lo);
        o.y = *reinterpret_cast<uint32_t*>(&hi);
        out[i] = o;
    }
}

// concat 3 bias vectors [1024] -> [3072]
__global__ void bcat_k(const float* __restrict__ a, const float* __restrict__ b,
                       const float* __restrict__ c, float* __restrict__ o) {
    const int i = blockIdx.x * blockDim.x + threadIdx.x;   // 0..1023
    o[i] = a[i]; o[i + 1024] = b[i]; o[i + 2048] = c[i];
}

// ---------------------------------------------------------------------------
// Per-batch transpose: out[b][h][s] = in[b][s][h]  (in = V slice, stride 3072)
// ---------------------------------------------------------------------------
__global__ void transpose_k(const bf16* __restrict__ in, bf16* __restrict__ out) {
    __shared__ bf16 t[32][33];
    const long long b = blockIdx.z;
    const bf16* ip = in  + b * 2048LL * 3072;
    bf16*       op = out + b * 2048LL * 1024;
    const int h0 = blockIdx.x * 32;
    const int s0 = blockIdx.y * 32;
    for (int i = threadIdx.y; i < 32; i += 8)
        t[i][threadIdx.x] = ip[(long long)(s0 + i) * 3072 + h0 + threadIdx.x];
    __syncthreads();
    for (int i = threadIdx.y; i < 32; i += 8)
        op[(long long)(h0 + i) * 2048 + s0 + threadIdx.x] = t[threadIdx.x][i];
}

// ---------------------------------------------------------------------------
// Row softmax over 2048 bf16, in place. One block (256 thr) per row.
// ---------------------------------------------------------------------------
__global__ void softmax_k(bf16* __restrict__ S) {
    const long long row = blockIdx.x;
    bf16* p = S + row * 2048;
    const int tid = threadIdx.x;

    uint4 u = reinterpret_cast<uint4*>(p)[tid];
    __nv_bfloat162* hp = reinterpret_cast<__nv_bfloat162*>(&u);
    float v[8];
#pragma unroll
    for (int i = 0; i < 4; ++i) {
        float2 f = __bfloat1622float2(hp[i]);
        v[2 * i] = f.x; v[2 * i + 1] = f.y;
    }
    float m = v[0];
#pragma unroll
    for (int i = 1; i < 8; ++i) m = fmaxf(m, v[i]);
#pragma unroll
    for (int o = 16; o > 0; o >>= 1) m = fmaxf(m, __shfl_xor_sync(0xffffffffu, m, o));
    __shared__ float red[8];
    if ((tid & 31) == 0) red[tid >> 5] = m;
    __syncthreads();
    float mm = red[0];
#pragma unroll
    for (int j = 1; j < 8; ++j) mm = fmaxf(mm, red[j]);

    float s = 0.f;
#pragma unroll
    for (int i = 0; i < 8; ++i) { v[i] = __expf(v[i] - mm); s += v[i]; }
#pragma unroll
    for (int o = 16; o > 0; o >>= 1) s += __shfl_xor_sync(0xffffffffu, s, o);
    __syncthreads();
    if ((tid & 31) == 0) red[tid >> 5] = s;
    __syncthreads();
    float ss = 0.f;
#pragma unroll
    for (int j = 0; j < 8; ++j) ss += red[j];
    const float inv = 1.0f / ss;

#pragma unroll
    for (int i = 0; i < 4; ++i)
        hp[i] = __floats2bfloat162_rn(v[2 * i] * inv, v[2 * i + 1] * inv);
    reinterpret_cast<uint4*>(p)[tid] = u;
}

// ---------------------------------------------------------------------------
// Row LayerNorm over 1024 fp32. One block (256 thr) per row.
// ---------------------------------------------------------------------------
__global__ void ln_k(const float* __restrict__ in, const float* __restrict__ gamma,
                     const float* __restrict__ beta, float* __restrict__ out) {
    const long long row = blockIdx.x;
    const int tid = threadIdx.x;
    const float4 v = reinterpret_cast<const float4*>(in + row * 1024)[tid];
    float s = v.x + v.y + v.z + v.w;
    float q = v.x * v.x + v.y * v.y + v.z * v.z + v.w * v.w;
#pragma unroll
    for (int o = 16; o > 0; o >>= 1) {
        s += __shfl_xor_sync(0xffffffffu, s, o);
        q += __shfl_xor_sync(0xffffffffu, q, o);
    }
    __shared__ float redS[8], redQ[8];
    if ((tid & 31) == 0) { redS[tid >> 5] = s; redQ[tid >> 5] = q; }
    __syncthreads();
    float S = 0.f, Q = 0.f;
#pragma unroll
    for (int j = 0; j < 8; ++j) { S += redS[j]; Q += redQ[j]; }
    const float mu  = S * (1.0f / 1024.0f);
    const float var = Q * (1.0f / 1024.0f) - mu * mu;
    const float rs  = rsqrtf(var + 1e-5f);
    const float4 g4 = reinterpret_cast<const float4*>(gamma)[tid];
    const float4 b4 = reinterpret_cast<const float4*>(beta)[tid];
    float4 o;
    o.x = (v.x - mu) * rs * g4.x + b4.x;
    o.y = (v.y - mu) * rs * g4.y + b4.y;
    o.z = (v.z - mu) * rs * g4.z + b4.z;
    o.w = (v.w - mu) * rs * g4.w + b4.w;
    reinterpret_cast<float4*>(out + row * 1024)[tid] = o;
}

// ---------------------------------------------------------------------------
// NT GEMM on mma.sync tensor cores (bf16 in, fp32 accum):
//   C[z][m][n] (+epi) = sum_k A[z][m][k] * B[z][n][k]
// Block tile 128x128x64 (BK=64 -> half the syncs of BK=32), 8 warps (2x4),
// warp tile 64x32 (4x4 m16n8k16), 2-stage cp.async double buffer,
// ONE syncthreads per k-tile, x4 ldmatrix for A+B,
// padded smem row stride 72 bf16 (144 B: 16B-aligned, conflict-free),
// __launch_bounds__(256,2) -> 2 CTAs/SM.
// MODE 0: +bias -> bf16 | 1: *scale -> bf16 | 2: plain -> bf16
// MODE 3: +bias +fp32 residual -> fp32
// ---------------------------------------------------------------------------
#define BM 128
#define BN 128
#define BK 64
#define NS 2
#define SAPAD 72
#define ROW_B   (SAPAD * 2)                  // 144 B
#define TILE_B  (128 * ROW_B)                // 18432 B (one operand, one stage)
#define STAGE_B (2 * TILE_B)                 // 36864 B
#define SMEM_DYN (NS * STAGE_B)              // 73728 B

__device__ __forceinline__ void load_stage(uint32_t sbase,
                                           const bf16* __restrict__ Ab, int lda,
                                           const bf16* __restrict__ Bb, int ldb,
                                           int k0, int tid) {
    // A: 128 rows x 8 chunks of 16B = 1024 ops / 256 thr
#pragma unroll
    for (int i = 0; i < 4; ++i) {
        const int idx = tid + i * 256;
        const int r = idx >> 3, c = idx & 7;
        const uint32_t dst = sbase + (uint32_t)(r * ROW_B + c * 16);
        const bf16* src = Ab + (long long)r * lda + (k0 + c * 8);
        asm volatile("cp.async.cg.shared.global [%0], [%1], 16;\n" :: "r"(dst), "l"(src));
    }
    // B
#pragma unroll
    for (int i = 0; i < 4; ++i) {
        const int idx = tid + i * 256;
        const int r = idx >> 3, c = idx & 7;
        const uint32_t dst = sbase + TILE_B + (uint32_t)(r * ROW_B + c * 16);
        const bf16* src = Bb + (long long)r * ldb + (k0 + c * 8);
        asm volatile("cp.async.cg.shared.global [%0], [%1], 16;\n" :: "r"(dst), "l"(src));
    }
    asm volatile("cp.async.commit_group;\n");
}

template <int MODE>
__global__ __launch_bounds__(256, 2) void gemm_nt(
    const bf16* __restrict__ A, int lda, long long sAz,
    const bf16* __restrict__ Bm, int ldb, long long sBz,
    void* __restrict__ Cv, int ldc, long long sCz,
    int K,
    const float* __restrict__ bias,
    const float* __restrict__ resid, int ldr,
    float scale) {
    extern __shared__ __align__(16) char dynsmem[];

    const int tid  = threadIdx.x;
    const int lane = tid & 31;
    const int warp = tid >> 5;
    const int wm   = warp >> 2;   // 0..1  (64 rows each)
    const int wn   = warp & 3;    // 0..3  (32 cols each)
    const long long z = blockIdx.z;

    const bf16* Ab = A  + z * sAz + (long long)blockIdx.y * BM * lda;
    const bf16* Bb = Bm + z * sBz + (long long)blockIdx.x * BN * ldb;

    const uint32_t sbase = (uint32_t)__cvta_generic_to_shared(dynsmem);

    float acc[4][4][4];
#pragma unroll
    for (int a = 0; a < 4; ++a)
#pragma unroll
        for (int b = 0; b < 4; ++b)
#pragma unroll
            for (int c = 0; c < 4; ++c) acc[a][b][c] = 0.f;

    const int T = K >> 6;   // BK = 64

    // prologue: stage 0
    load_stage(sbase, Ab, lda, Bb, ldb, 0, tid);

    // precomputed smem read offsets
    const uint32_t a_off = (uint32_t)(((lane & 7) + ((lane >> 3) & 1) * 8) * ROW_B
                                      + ((lane >> 4) << 3) * 2);
    // B x4: grp = lane>>3 : mat0=(n0-7,k0-7) mat1=(n0-7,k8-15) mat2=(n8-15,k0-7) mat3=(n8-15,k8-15)
    const int bgrp = lane >> 3, brr = lane & 7;
    const uint32_t b_off = (uint32_t)((((bgrp >> 1) & 1) * 8 + brr) * ROW_B
                                      + ((bgrp & 1) * 8) * 2);

    for (int t = 0; t < T; ++t) {
        asm volatile("cp.async.wait_group 0;\n" ::: "memory");
        __syncthreads();   // stage t visible to all; stage t-1 reads complete

        if (t + 1 < T)
            load_stage(sbase + ((t + 1) & 1) * STAGE_B, Ab, lda, Bb, ldb, (t + 1) * BK, tid);
        else
            asm volatile("cp.async.commit_group;\n");

        const uint32_t aB = sbase + (t & 1) * STAGE_B + wm * 64 * ROW_B + a_off;
        const uint32_t bB = sbase + (t & 1) * STAGE_B + TILE_B + wn * 32 * ROW_B + b_off;
#pragma unroll
        for (int ks = 0; ks < 4; ++ks) {
            const uint32_t kboff = (uint32_t)(ks * 16 * 2);
            uint32_t af[4][4];
#pragma unroll
            for (int mt = 0; mt < 4; ++mt) {
                const uint32_t ad = aB + mt * 16 * ROW_B + kboff;
                asm volatile(
                    "ldmatrix.sync.aligned.m8n8.x4.shared.b16 {%0,%1,%2,%3}, [%4];"
                    : "=r"(af[mt][0]), "=r"(af[mt][1]), "=r"(af[mt][2]), "=r"(af[mt][3])
                    : "r"(ad));
            }
            uint32_t bfr[4][2];
#pragma unroll
            for (int np = 0; np < 2; ++np) {
                const uint32_t bd = bB + np * 16 * ROW_B + kboff;
                uint32_t r0, r1, r2, r3;
                asm volatile(
                    "ldmatrix.sync.aligned.m8n8.x4.shared.b16 {%0,%1,%2,%3}, [%4];"
                    : "=r"(r0), "=r"(r1), "=r"(r2), "=r"(r3)
                    : "r"(bd));
                bfr[2 * np][0]     = r0; bfr[2 * np][1]     = r1;
                bfr[2 * np + 1][0] = r2; bfr[2 * np + 1][1] = r3;
            }
#pragma unroll
            for (int mt = 0; mt < 4; ++mt)
#pragma unroll
                for (int nt = 0; nt < 4; ++nt)
                    asm volatile(
                        "mma.sync.aligned.m16n8k16.row.col.f32.bf16.bf16.f32 "
                        "{%0,%1,%2,%3}, {%4,%5,%6,%7}, {%8,%9}, {%0,%1,%2,%3};"
                        : "+f"(acc[mt][nt][0]), "+f"(acc[mt][nt][1]),
                          "+f"(acc[mt][nt][2]), "+f"(acc[mt][nt][3])
                        : "r"(af[mt][0]), "r"(af[mt][1]), "r"(af[mt][2]), "r"(af[mt][3]),
                          "r"(bfr[nt][0]), "r"(bfr[nt][1]));
        }
    }

    // Epilogue. acc[.][.][0]=(r0,c0) [1]=(r0,c0+1) [2]=(r0+8,c0) [3]=(r0+8,c0+1)
    const int g  = lane >> 2;
    const int tq = lane & 3;
    const int rbase = blockIdx.y * BM + wm * 64;
    const int cbase = blockIdx.x * BN + wn * 32;
#pragma unroll
    for (int mt = 0; mt < 4; ++mt) {
#pragma unroll
        for (int nt = 0; nt < 4; ++nt) {
            const int r0 = rbase + mt * 16 + g;
            const int c0 = cbase + nt * 8 + 2 * tq;
            float v00 = acc[mt][nt][0], v01 = acc[mt][nt][1];
            float v10 = acc[mt][nt][2], v11 = acc[mt][nt][3];
            if (MODE == 1) { v00 *= scale; v01 *= scale; v10 *= scale; v11 *= scale; }
            if (MODE == 0 || MODE == 3) {
                const float b0 = bias[c0], b1 = bias[c0 + 1];
                v00 += b0; v01 += b1; v10 += b0; v11 += b1;
            }
            if (MODE == 3) {
                float* Cf = (float*)Cv + z * sCz;
                const long long i0 = (long long)r0 * ldc + c0;
                const long long i1 = (long long)(r0 + 8) * ldc + c0;
                const float2 ra = reinterpret_cast<const float2*>(resid + (long long)r0 * ldr + c0)[0];
                const float2 rb = reinterpret_cast<const float2*>(resid + (long long)(r0 + 8) * ldr + c0)[0];
                reinterpret_cast<float2*>(Cf + i0)[0] = make_float2(v00 + ra.x, v01 + ra.y);
                reinterpret_cast<float2*>(Cf + i1)[0] = make_float2(v10 + rb.x, v11 + rb.y);
            } else {
                bf16* Cb = (bf16*)Cv + z * sCz;
                reinterpret_cast<__nv_bfloat162*>(Cb + (long long)r0 * ldc + c0)[0] =
                    __floats2bfloat162_rn(v00, v01);
                reinterpret_cast<__nv_bfloat162*>(Cb + (long long)(r0 + 8) * ldc + c0)[0] =
                    __floats2bfloat162_rn(v10, v11);
            }
        }
    }
}

// ---------------------------------------------------------------------------
// Host orchestration
// ---------------------------------------------------------------------------
extern "C" void kernel_launch(void* const* d_in, const int* in_sizes, int n_in,
                              void* d_out, int out_size) {
    (void)in_sizes; (void)n_in; (void)out_size;
    const float* x     = (const float*)d_in[0];
    const float* Wq    = (const float*)d_in[1];
    const float* bq    = (const float*)d_in[2];
    const float* Wk    = (const float*)d_in[3];
    const float* bk    = (const float*)d_in[4];
    const float* Wv    = (const float*)d_in[5];
    const float* bv    = (const float*)d_in[6];
    const float* Wo    = (const float*)d_in[7];
    const float* bo    = (const float*)d_in[8];
    const float* gamma = (const float*)d_in[9];
    const float* beta  = (const float*)d_in[10];

    void* p;
    bf16 *xb, *wqkv, *wo, *qkv, *vtb, *sb, *wtb;
    float *bqkv, *pre;
    cudaGetSymbolAddress(&p, g_xb);   xb   = (bf16*)p;
    cudaGetSymbolAddress(&p, g_wqkv); wqkv = (bf16*)p;
    cudaGetSymbolAddress(&p, g_bqkv); bqkv = (float*)p;
    cudaGetSymbolAddress(&p, g_wo);   wo   = (bf16*)p;
    cudaGetSymbolAddress(&p, g_qkv);  qkv  = (bf16*)p;
    cudaGetSymbolAddress(&p, g_vt);   vtb  = (bf16*)p;
    cudaGetSymbolAddress(&p, g_s);    sb   = (bf16*)p;
    cudaGetSymbolAddress(&p, g_w);    wtb  = (bf16*)p;
    cudaGetSymbolAddress(&p, g_pre);  pre  = (float*)p;

    cudaFuncSetAttribute(gemm_nt<0>, cudaFuncAttributeMaxDynamicSharedMemorySize, SMEM_DYN);
    cudaFuncSetAttribute(gemm_nt<1>, cudaFuncAttributeMaxDynamicSharedMemorySize, SMEM_DYN);
    cudaFuncSetAttribute(gemm_nt<2>, cudaFuncAttributeMaxDynamicSharedMemorySize, SMEM_DYN);
    cudaFuncSetAttribute(gemm_nt<3>, cudaFuncAttributeMaxDynamicSharedMemorySize, SMEM_DYN);

    // 1) fp32 -> bf16 conversions; weights go into concatenated W_qkv
    cvt_k<<<2048, 256>>>((const float4*)x,  (uint2*)xb,               16384 * 256);
    cvt_k<<<512,  256>>>((const float4*)Wq, (uint2*)(wqkv),           1024 * 256);
    cvt_k<<<512,  256>>>((const float4*)Wk, (uint2*)(wqkv + 1024LL*1024), 1024 * 256);
    cvt_k<<<512,  256>>>((const float4*)Wv, (uint2*)(wqkv + 2048LL*1024), 1024 * 256);
    cvt_k<<<512,  256>>>((const float4*)Wo, (uint2*)wo,               1024 * 256);
    bcat_k<<<4, 256>>>(bq, bk, bv, bqkv);

    const dim3 blk(256);

    // 2) fused QKV: [16384,3072] = x @ [Wq|Wk|Wv]^T + b
    const dim3 gQKV(3072 / BN, 16384 / BM, 1);
    gemm_nt<0><<<gQKV, blk, SMEM_DYN>>>(xb, 1024, 0, wqkv, 1024, 0,
                                        qkv, 3072, 0, 1024, bqkv, nullptr, 0, 0.f);

    // 3) V -> V^T per batch (V = qkv cols 2048..3071)
    transpose_k<<<dim3(1024 / 32, 2048 / 32, 8), dim3(32, 8)>>>(qkv + 2048, vtb);

    // 4) scores[b] = (Q[b] @ K[b]^T) * 1/sqrt(1024)
    const dim3 gS(2048 / BN, 2048 / BM, 8);
    gemm_nt<1><<<gS, blk, SMEM_DYN>>>(qkv,        3072, 2048LL * 3072,
                                      qkv + 1024, 3072, 2048LL * 3072,
                                      sb, 2048, 2048LL * 2048, 1024,
                                      nullptr, nullptr, 0, 0.03125f);

    // 5) softmax rows (in place, fp32 math)
    softmax_k<<<16384, 256>>>(sb);

    // 6) weighted[b] = attn[b] @ V[b]   (NT against V^T)
    const dim3 gW(1024 / BN, 2048 / BM, 8);
    gemm_nt<2><<<gW, blk, SMEM_DYN>>>(sb, 2048, 2048LL * 2048, vtb, 2048, 1024LL * 2048,
                                      wtb, 1024, 2048LL * 1024, 2048, nullptr, nullptr, 0, 0.f);

    // 7) pre = weighted @ Wo^T + bo + x   (fp32 residual, fp32 out)
    const dim3 gO(1024 / BN, 16384 / BM, 1);
    gemm_nt<3><<<gO, blk, SMEM_DYN>>>(wtb, 1024, 0, wo, 1024, 0, pre, 1024, 0, 1024, bo, x, 1024, 0.f);

    // 8) LayerNorm -> d_out
    ln_k<<<16384, 256>>>(pre, gamma, beta, (float*)d_out);
}